// round 5
// baseline (speedup 1.0000x reference)
#include <cuda_runtime.h>
#include <math.h>

// Problem constants
#define BSZ   4096
#define NCGC  2

#define MAIN_BLOCK 256   // 8 warps
#define WPB 8            // warps per block (1 graph per warp)

// Device-global scratch (allocation-free per harness rules)
__device__ float g_A2[7 * 128];          // masked sigmoid attention, layer 2
__device__ float g_p2[2 * 2 * 128];      // [c][j] layer-2 support rows, nodes 0,1
__device__ float g_table[2 * 441 * 128]; // [c][key] layer-2 support, step nodes

// ---------------------------------------------------------------------------
// Kernel 1: fused precompute + table build. One key per block, grid (441, 2).
// Every block redundantly recomputes the tiny per-c ingredients (weight loads
// are L2-broadcast); block x==0 also writes the A2 / p2 tables.
// key = (op0*3 + fc0)*21 + (op1*3 + fc1), fc = min(f, 2).
// table[c][key] = relu(sup1b + A1[op0]*sup(fc0) + A1[op1]*sup(fc1)) @ W2
// ---------------------------------------------------------------------------
__global__ void build_kernel(
    const float* __restrict__ init_emb,   // (2,2,48)
    const float* __restrict__ other_emb,  // (2,1,48)
    const float* __restrict__ op_embs,    // (7,48)
    const float* __restrict__ Wx,         // (48,48)
    const float* __restrict__ bx,         // (48)
    const float* __restrict__ W1,         // (48,128)
    const float* __restrict__ Wa1,        // (48,128)
    const float* __restrict__ ba1,        // (128)
    const float* __restrict__ W2,         // (128,128)
    const float* __restrict__ Wa2,        // (48,128)
    const float* __restrict__ ba2)        // (128)
{
  const int d = threadIdx.x;
  const int c = blockIdx.y;

  __shared__ float ope[7 * 48];
  __shared__ float y0[3 * 48];   // rows: 0,1 = init nodes, 2 = step node
  __shared__ float sh[128];

  for (int i = d; i < 7 * 48; i += 128) ope[i] = __ldg(&op_embs[i]);

  // One flat parallel phase for all three y0 rows (144 items over 128 threads)
  for (int it = d; it < 144; it += 128) {
    const int r = it / 48, h = it - r * 48;
    const float* e = (r < 2) ? (init_emb + (c * 2 + r) * 48)
                             : (other_emb + c * 48);
    float t = __ldg(&bx[h]);
#pragma unroll
    for (int k = 0; k < 48; ++k) t += __ldg(&e[k]) * __ldg(&Wx[k * 48 + h]);
    y0[it] = t;
  }
  __syncthreads();

  // Layer-1 support rows (shared W1-column loads across the 3 rows)
  float s0 = 0.f, s1 = 0.f, sb = 0.f;
#pragma unroll
  for (int h = 0; h < 48; ++h) {
    const float w = __ldg(&W1[h * 128 + d]);
    s0 += y0[h] * w;
    s1 += y0[48 + h] * w;
    sb += y0[96 + h] * w;
  }

  // A1 attention for this block's key ops only (op0, op1)
  const int key = blockIdx.x;
  const int sA = key / 21, sB = key - sA * 21;
  const int op0 = sA / 3, fc0 = sA - op0 * 3;
  const int op1 = sB / 3, fc1 = sB - op1 * 3;

  float a1v0, a1v1;
  {
    float acc0 = __ldg(&ba1[d]), acc1 = acc0;
#pragma unroll
    for (int k = 0; k < 48; ++k) {
      const float w = __ldg(&Wa1[k * 128 + d]);
      acc0 += ope[op0 * 48 + k] * w;
      acc1 += ope[op1 * 48 + k] * w;
    }
    a1v0 = (op0 == 0) ? 0.f : 1.f / (1.f + expf(-acc0));
    a1v1 = (op1 == 0) ? 0.f : 1.f / (1.f + expf(-acc1));
  }

  // Block 0 extras: A2 attention table + p2 rows for init nodes
  if (blockIdx.x == 0) {
    float acc[7];
#pragma unroll
    for (int op = 0; op < 7; ++op) acc[op] = __ldg(&ba2[d]);
    for (int k = 0; k < 48; ++k) {
      const float w = __ldg(&Wa2[k * 128 + d]);
#pragma unroll
      for (int op = 0; op < 7; ++op) acc[op] += ope[op * 48 + k] * w;
    }
    if (c == 0) {
      g_A2[d] = 0.f;
#pragma unroll
      for (int op = 1; op < 7; ++op)
        g_A2[op * 128 + d] = 1.f / (1.f + expf(-acc[op]));
    }
#pragma unroll
    for (int j = 0; j < 2; ++j) {
      __syncthreads();
      sh[d] = fmaxf(j == 0 ? s0 : s1, 0.f);
      __syncthreads();
      float p0 = 0.f, p1 = 0.f, p2a = 0.f, p3 = 0.f;
#pragma unroll
      for (int h = 0; h < 128; h += 4) {
        p0 += sh[h]     * __ldg(&W2[(h)     * 128 + d]);
        p1 += sh[h + 1] * __ldg(&W2[(h + 1) * 128 + d]);
        p2a+= sh[h + 2] * __ldg(&W2[(h + 2) * 128 + d]);
        p3 += sh[h + 3] * __ldg(&W2[(h + 3) * 128 + d]);
      }
      g_p2[(c * 2 + j) * 128 + d] = (p0 + p1) + (p2a + p3);
    }
  }

  // This block's single key
  {
    const float v0 = (fc0 == 0) ? s0 : (fc0 == 1) ? s1 : sb;
    const float v1 = (fc1 == 0) ? s0 : (fc1 == 1) ? s1 : sb;
    const float y = sb + a1v0 * v0 + a1v1 * v1;
    __syncthreads();
    sh[d] = fmaxf(y, 0.f);
    __syncthreads();
    float a0 = 0.f, a1_ = 0.f, a2 = 0.f, a3 = 0.f;
#pragma unroll
    for (int h = 0; h < 128; h += 4) {
      a0  += sh[h]     * __ldg(&W2[(h)     * 128 + d]);
      a1_ += sh[h + 1] * __ldg(&W2[(h + 1) * 128 + d]);
      a2  += sh[h + 2] * __ldg(&W2[(h + 2) * 128 + d]);
      a3  += sh[h + 3] * __ldg(&W2[(h + 3) * 128 + d]);
    }
    g_table[(c * 441 + key) * 128 + d] = (a0 + a1_) + (a2 + a3);
  }

#if __CUDA_ARCH__ >= 900
  cudaTriggerProgrammaticLaunchCompletion();
#endif
}

// ---------------------------------------------------------------------------
// Kernel 2 (PDL consumer): one warp per graph, lane owns 4 feature dims.
// Pre-sync phase: arch loads + key math (overlaps build via PDL).
// A2 attention rows read directly from global (L1-resident, 3.5 KB).
// Per-warp smem scratch rows [p2_0, p2_1, r0, r1, r2] make src(f) one LDS.128.
// ---------------------------------------------------------------------------
__global__ void __launch_bounds__(MAIN_BLOCK)
gcn_main_kernel(const int* __restrict__ archs, float* __restrict__ out) {
  __shared__ float4 scratch[WPB][5 * 32];

  const int tid  = threadIdx.x;
  const int lane = tid & 31;
  const int w    = tid >> 5;

  const int task = blockIdx.x * WPB + w;   // 0..8191 (one graph each)
  const int c    = task >> 12;             // warp-uniform
  const int b    = task & (BSZ - 1);

  // ---- pre-dependency phase: arch loads + key computation ----
  const int4* a = (const int4*)(archs + (size_t)(b * NCGC + c) * 16);
  const int4 fA = __ldg(a);      // f[0..3]
  const int4 fB = __ldg(a + 1);  // f[4..7]
  const int4 oA = __ldg(a + 2);  // op[0..3]
  const int4 oB = __ldg(a + 3);  // op[4..7]

  const int k0 = (oA.x * 3 + min(fA.x, 2)) * 21 + oA.y * 3 + min(fA.y, 2);
  const int k1 = (oA.z * 3 + min(fA.z, 2)) * 21 + oA.w * 3 + min(fA.w, 2);
  const int k2 = (oB.x * 3 + min(fB.x, 2)) * 21 + oB.y * 3 + min(fB.y, 2);
  const int k3 = (oB.z * 3 + min(fB.z, 2)) * 21 + oB.w * 3 + min(fB.w, 2);

  // ---- wait for build_kernel's writes ----
#if __CUDA_ARCH__ >= 900
  cudaGridDependencySynchronize();
#endif

  const float* __restrict__ tab = g_table + (size_t)c * 441 * 128;

  // Issue all 4 gathers immediately (independent LDG.128s)
  const float4 r0 = __ldg((const float4*)(tab + k0 * 128) + lane);
  const float4 r1 = __ldg((const float4*)(tab + k1 * 128) + lane);
  const float4 r2 = __ldg((const float4*)(tab + k2 * 128) + lane);
  const float4 r3 = __ldg((const float4*)(tab + k3 * 128) + lane);

  float4* scr = scratch[w];
  const float4* p2 = (const float4*)(g_p2 + c * 2 * 128);
  scr[lane]      = __ldg(p2 + lane);        // row 0 = node 0 support2
  scr[32 + lane] = __ldg(p2 + 32 + lane);   // row 1 = node 1 support2
  scr[64 + lane]  = r0;                     // row 2 = node 2
  scr[96 + lane]  = r1;                     // row 3 = node 3
  scr[128 + lane] = r2;                     // row 4 = node 4
  __syncwarp();

  float4 acc;
  acc.x = (r0.x + r1.x) + (r2.x + r3.x);
  acc.y = (r0.y + r1.y) + (r2.y + r3.y);
  acc.z = (r0.z + r1.z) + (r2.z + r3.z);
  acc.w = (r0.w + r1.w) + (r2.w + r3.w);

  const float4* __restrict__ A = (const float4*)g_A2;

#define EDGE(o, f)                                   \
  {                                                  \
    const float4 at = __ldg(&A[(o) * 32 + lane]);    \
    const float4 sv = scr[(f) * 32 + lane];          \
    acc.x += at.x * sv.x;                            \
    acc.y += at.y * sv.y;                            \
    acc.z += at.z * sv.z;                            \
    acc.w += at.w * sv.w;                            \
  }

  EDGE(oA.x, fA.x); EDGE(oA.y, fA.y);
  EDGE(oA.z, fA.z); EDGE(oA.w, fA.w);
  EDGE(oB.x, fB.x); EDGE(oB.y, fB.y);
  EDGE(oB.z, fB.z); EDGE(oB.w, fB.w);
#undef EDGE

  float4 res;
  res.x = acc.x * 0.25f; res.y = acc.y * 0.25f;
  res.z = acc.z * 0.25f; res.w = acc.w * 0.25f;
  ((float4*)(out + (size_t)(b * NCGC + c) * 128))[lane] = res;
}

// ---------------------------------------------------------------------------
extern "C" void kernel_launch(void* const* d_in, const int* in_sizes, int n_in,
                              void* d_out, int out_size) {
  const int*   archs     = (const int*)d_in[0];
  const float* init_emb  = (const float*)d_in[1];
  const float* other_emb = (const float*)d_in[2];
  const float* op_embs   = (const float*)d_in[3];
  const float* Wx        = (const float*)d_in[4];
  const float* bx        = (const float*)d_in[5];
  const float* W1        = (const float*)d_in[6];
  const float* Wa1       = (const float*)d_in[7];
  const float* ba1       = (const float*)d_in[8];
  const float* W2        = (const float*)d_in[9];
  const float* Wa2       = (const float*)d_in[10];
  const float* ba2       = (const float*)d_in[11];
  float* out = (float*)d_out;

  build_kernel<<<dim3(441, NCGC), 128>>>(init_emb, other_emb, op_embs, Wx, bx,
                                         W1, Wa1, ba1, W2, Wa2, ba2);

  // Programmatic Dependent Launch: main starts while build runs; each thread
  // blocks at cudaGridDependencySynchronize until build completes.
  cudaLaunchConfig_t cfg = {};
  cfg.gridDim  = dim3(BSZ * NCGC / WPB);   // 1024 blocks
  cfg.blockDim = dim3(MAIN_BLOCK);
  cudaLaunchAttribute attr[1];
  attr[0].id = cudaLaunchAttributeProgrammaticStreamSerialization;
  attr[0].val.programmaticStreamSerializationAllowed = 1;
  cfg.attrs = attr;
  cfg.numAttrs = 1;
  cudaLaunchKernelEx(&cfg, gcn_main_kernel, archs, out);
}

// round 6
// speedup vs baseline: 1.0592x; 1.0592x over previous
#include <cuda_runtime.h>
#include <math.h>

// Problem constants
#define BSZ   4096
#define NCGC  2

#define MAIN_BLOCK 256   // 8 warps
#define WPB 8            // warps per block (1 graph per warp)

// Device-global scratch (allocation-free per harness rules)
// C[c][op][j][128]: j<2 -> A2[op]*p2[c][j] ; j in 2..4 -> A2[op]
__device__ float g_C[2 * 7 * 5 * 128];
__device__ float g_table[2 * 441 * 128]; // [c][key] layer-2 support, step nodes

// ---------------------------------------------------------------------------
// Kernel 1: fused precompute + table build. One key per block, grid (441, 2).
// Every block redundantly recomputes the tiny per-c ingredients (weight loads
// are L2-broadcast); block x==0 also builds the combined coefficient table C.
// key = (op0*3 + fc0)*21 + (op1*3 + fc1), fc = min(f, 2).
// table[c][key] = relu(sup1b + A1[op0]*sup(fc0) + A1[op1]*sup(fc1)) @ W2
// ---------------------------------------------------------------------------
__global__ void build_kernel(
    const float* __restrict__ init_emb,   // (2,2,48)
    const float* __restrict__ other_emb,  // (2,1,48)
    const float* __restrict__ op_embs,    // (7,48)
    const float* __restrict__ Wx,         // (48,48)
    const float* __restrict__ bx,         // (48)
    const float* __restrict__ W1,         // (48,128)
    const float* __restrict__ Wa1,        // (48,128)
    const float* __restrict__ ba1,        // (128)
    const float* __restrict__ W2,         // (128,128)
    const float* __restrict__ Wa2,        // (48,128)
    const float* __restrict__ ba2)        // (128)
{
  const int d = threadIdx.x;
  const int c = blockIdx.y;

  __shared__ float ope[7 * 48];
  __shared__ float y0[3 * 48];   // rows: 0,1 = init nodes, 2 = step node
  __shared__ float sh[128];

  for (int i = d; i < 7 * 48; i += 128) ope[i] = __ldg(&op_embs[i]);

  // One flat parallel phase for all three y0 rows (144 items over 128 threads)
  for (int it = d; it < 144; it += 128) {
    const int r = it / 48, h = it - r * 48;
    const float* e = (r < 2) ? (init_emb + (c * 2 + r) * 48)
                             : (other_emb + c * 48);
    float t = __ldg(&bx[h]);
#pragma unroll
    for (int k = 0; k < 48; ++k) t += __ldg(&e[k]) * __ldg(&Wx[k * 48 + h]);
    y0[it] = t;
  }
  __syncthreads();

  // Layer-1 support rows (shared W1-column loads across the 3 rows)
  float s0 = 0.f, s1 = 0.f, sb = 0.f;
#pragma unroll
  for (int h = 0; h < 48; ++h) {
    const float w = __ldg(&W1[h * 128 + d]);
    s0 += y0[h] * w;
    s1 += y0[48 + h] * w;
    sb += y0[96 + h] * w;
  }

  // A1 attention for this block's key ops only (op0, op1)
  const int key = blockIdx.x;
  const int sA = key / 21, sB = key - sA * 21;
  const int op0 = sA / 3, fc0 = sA - op0 * 3;
  const int op1 = sB / 3, fc1 = sB - op1 * 3;

  float a1v0, a1v1;
  {
    float acc0 = __ldg(&ba1[d]), acc1 = acc0;
#pragma unroll
    for (int k = 0; k < 48; ++k) {
      const float w = __ldg(&Wa1[k * 128 + d]);
      acc0 += ope[op0 * 48 + k] * w;
      acc1 += ope[op1 * 48 + k] * w;
    }
    a1v0 = (op0 == 0) ? 0.f : 1.f / (1.f + expf(-acc0));
    a1v1 = (op1 == 0) ? 0.f : 1.f / (1.f + expf(-acc1));
  }

  // Block 0 extras: A2 attention + p2 rows -> combined coefficient table C
  if (blockIdx.x == 0) {
    float a2v[7];
    {
      float acc[7];
#pragma unroll
      for (int op = 0; op < 7; ++op) acc[op] = __ldg(&ba2[d]);
      for (int k = 0; k < 48; ++k) {
        const float w = __ldg(&Wa2[k * 128 + d]);
#pragma unroll
        for (int op = 0; op < 7; ++op) acc[op] += ope[op * 48 + k] * w;
      }
      a2v[0] = 0.f;
#pragma unroll
      for (int op = 1; op < 7; ++op) a2v[op] = 1.f / (1.f + expf(-acc[op]));
    }
    // p2[j] = relu(sup1[c][j]) @ W2 for init nodes j=0,1
    float p2v[2];
#pragma unroll
    for (int j = 0; j < 2; ++j) {
      __syncthreads();
      sh[d] = fmaxf(j == 0 ? s0 : s1, 0.f);
      __syncthreads();
      float p0 = 0.f, p1 = 0.f, p2a = 0.f, p3 = 0.f;
#pragma unroll
      for (int h = 0; h < 128; h += 4) {
        p0 += sh[h]     * __ldg(&W2[(h)     * 128 + d]);
        p1 += sh[h + 1] * __ldg(&W2[(h + 1) * 128 + d]);
        p2a+= sh[h + 2] * __ldg(&W2[(h + 2) * 128 + d]);
        p3 += sh[h + 3] * __ldg(&W2[(h + 3) * 128 + d]);
      }
      p2v[j] = (p0 + p1) + (p2a + p3);
    }
    float* Cc = g_C + c * 7 * 5 * 128;
#pragma unroll
    for (int op = 0; op < 7; ++op) {
      Cc[(op * 5 + 0) * 128 + d] = a2v[op] * p2v[0];
      Cc[(op * 5 + 1) * 128 + d] = a2v[op] * p2v[1];
      Cc[(op * 5 + 2) * 128 + d] = a2v[op];
      Cc[(op * 5 + 3) * 128 + d] = a2v[op];
      Cc[(op * 5 + 4) * 128 + d] = a2v[op];
    }
  }

  // This block's single key
  {
    const float v0 = (fc0 == 0) ? s0 : (fc0 == 1) ? s1 : sb;
    const float v1 = (fc1 == 0) ? s0 : (fc1 == 1) ? s1 : sb;
    const float y = sb + a1v0 * v0 + a1v1 * v1;
    __syncthreads();
    sh[d] = fmaxf(y, 0.f);
    __syncthreads();
    float a0 = 0.f, a1_ = 0.f, a2 = 0.f, a3 = 0.f;
#pragma unroll
    for (int h = 0; h < 128; h += 4) {
      a0  += sh[h]     * __ldg(&W2[(h)     * 128 + d]);
      a1_ += sh[h + 1] * __ldg(&W2[(h + 1) * 128 + d]);
      a2  += sh[h + 2] * __ldg(&W2[(h + 2) * 128 + d]);
      a3  += sh[h + 3] * __ldg(&W2[(h + 3) * 128 + d]);
    }
    g_table[(c * 441 + key) * 128 + d] = (a0 + a1_) + (a2 + a3);
  }

#if __CUDA_ARCH__ >= 900
  cudaTriggerProgrammaticLaunchCompletion();
#endif
}

// ---------------------------------------------------------------------------
// Kernel 2 (PDL consumer): one warp per graph, lane owns 4 feature dims.
// No shared memory. Per edge: ONE LDG.128 from the combined table C, then
// either a plain add (f<2, p2 folded into C) or an FMA with a table row
// selected from registers (f in 2..4, warp-uniform select).
// ---------------------------------------------------------------------------
__global__ void __launch_bounds__(MAIN_BLOCK)
gcn_main_kernel(const int* __restrict__ archs, float* __restrict__ out) {
  const int tid  = threadIdx.x;
  const int lane = tid & 31;
  const int w    = tid >> 5;

  const int task = blockIdx.x * WPB + w;   // 0..8191 (one graph each)
  const int c    = task >> 12;             // warp-uniform
  const int b    = task & (BSZ - 1);

  // ---- pre-dependency phase: arch loads + key computation ----
  const int4* a = (const int4*)(archs + (size_t)(b * NCGC + c) * 16);
  const int4 fA = __ldg(a);      // f[0..3]
  const int4 fB = __ldg(a + 1);  // f[4..7]
  const int4 oA = __ldg(a + 2);  // op[0..3]
  const int4 oB = __ldg(a + 3);  // op[4..7]

  const int k0 = (oA.x * 3 + min(fA.x, 2)) * 21 + oA.y * 3 + min(fA.y, 2);
  const int k1 = (oA.z * 3 + min(fA.z, 2)) * 21 + oA.w * 3 + min(fA.w, 2);
  const int k2 = (oB.x * 3 + min(fB.x, 2)) * 21 + oB.y * 3 + min(fB.y, 2);
  const int k3 = (oB.z * 3 + min(fB.z, 2)) * 21 + oB.w * 3 + min(fB.w, 2);

  // ---- wait for build_kernel's writes ----
#if __CUDA_ARCH__ >= 900
  cudaGridDependencySynchronize();
#endif

  const float* __restrict__ tab = g_table + (size_t)c * 441 * 128;

  // Issue all 4 gathers immediately (independent LDG.128s)
  const float4 r0 = __ldg((const float4*)(tab + k0 * 128) + lane);
  const float4 r1 = __ldg((const float4*)(tab + k1 * 128) + lane);
  const float4 r2 = __ldg((const float4*)(tab + k2 * 128) + lane);
  const float4 r3 = __ldg((const float4*)(tab + k3 * 128) + lane);

  float4 acc;
  acc.x = (r0.x + r1.x) + (r2.x + r3.x);
  acc.y = (r0.y + r1.y) + (r2.y + r3.y);
  acc.z = (r0.z + r1.z) + (r2.z + r3.z);
  acc.w = (r0.w + r1.w) + (r2.w + r3.w);

  const float4* __restrict__ C4 = (const float4*)(g_C + c * 7 * 5 * 128);

#define EDGE(o, f)                                                     \
  {                                                                    \
    const float4 cr = __ldg(&C4[((o) * 5 + (f)) * 32 + lane]);         \
    if ((f) < 2) {                                                     \
      acc.x += cr.x; acc.y += cr.y; acc.z += cr.z; acc.w += cr.w;      \
    } else {                                                           \
      const float4 rv = ((f) == 2) ? r0 : (((f) == 3) ? r1 : r2);      \
      acc.x += cr.x * rv.x; acc.y += cr.y * rv.y;                      \
      acc.z += cr.z * rv.z; acc.w += cr.w * rv.w;                      \
    }                                                                  \
  }

  EDGE(oA.x, fA.x); EDGE(oA.y, fA.y);
  EDGE(oA.z, fA.z); EDGE(oA.w, fA.w);
  EDGE(oB.x, fB.x); EDGE(oB.y, fB.y);
  EDGE(oB.z, fB.z); EDGE(oB.w, fB.w);
#undef EDGE

  float4 res;
  res.x = acc.x * 0.25f; res.y = acc.y * 0.25f;
  res.z = acc.z * 0.25f; res.w = acc.w * 0.25f;
  ((float4*)(out + (size_t)(b * NCGC + c) * 128))[lane] = res;
}

// ---------------------------------------------------------------------------
extern "C" void kernel_launch(void* const* d_in, const int* in_sizes, int n_in,
                              void* d_out, int out_size) {
  const int*   archs     = (const int*)d_in[0];
  const float* init_emb  = (const float*)d_in[1];
  const float* other_emb = (const float*)d_in[2];
  const float* op_embs   = (const float*)d_in[3];
  const float* Wx        = (const float*)d_in[4];
  const float* bx        = (const float*)d_in[5];
  const float* W1        = (const float*)d_in[6];
  const float* Wa1       = (const float*)d_in[7];
  const float* ba1       = (const float*)d_in[8];
  const float* W2        = (const float*)d_in[9];
  const float* Wa2       = (const float*)d_in[10];
  const float* ba2       = (const float*)d_in[11];
  float* out = (float*)d_out;

  build_kernel<<<dim3(441, NCGC), 128>>>(init_emb, other_emb, op_embs, Wx, bx,
                                         W1, Wa1, ba1, W2, Wa2, ba2);

  // Programmatic Dependent Launch: main starts while build runs; each thread
  // blocks at cudaGridDependencySynchronize until build completes.
  cudaLaunchConfig_t cfg = {};
  cfg.gridDim  = dim3(BSZ * NCGC / WPB);   // 1024 blocks
  cfg.blockDim = dim3(MAIN_BLOCK);
  cudaLaunchAttribute attr[1];
  attr[0].id = cudaLaunchAttributeProgrammaticStreamSerialization;
  attr[0].val.programmaticStreamSerializationAllowed = 1;
  cfg.attrs = attr;
  cfg.numAttrs = 1;
  cudaLaunchKernelEx(&cfg, gcn_main_kernel, archs, out);
}